// round 1
// baseline (speedup 1.0000x reference)
#include <cuda_runtime.h>
#include <math.h>

#define BATCH  2
#define SEQ    2048
#define EMBED  1024
#define NHEADS 16
#define HDIM   64
#define MROWS  (BATCH*SEQ)   // 4096

// Scratch (allocation-free rule: __device__ globals)
__device__ float g_q[BATCH*NHEADS*SEQ*HDIM];    // [B,H,S,D]
__device__ float g_k[BATCH*NHEADS*SEQ*HDIM];
__device__ float g_v[BATCH*NHEADS*SEQ*HDIM];
__device__ float g_attn[MROWS*EMBED];           // [B,S,E]

// ---------------------------------------------------------------------------
// Fused QKV projection: y = x @ W, scattered to [B,H,S,D].
// 128x64 tile, BK=16, 256 threads, 8x4 per-thread.
// ---------------------------------------------------------------------------
__global__ __launch_bounds__(256) void qkv_kernel(
    const float* __restrict__ x,
    const float* __restrict__ Wq,
    const float* __restrict__ Wk,
    const float* __restrict__ Wv)
{
    __shared__ float As[16][132];   // [k][m], padded
    __shared__ float Bs[16][68];    // [k][n], padded

    const float* W   = (blockIdx.z == 0) ? Wq : (blockIdx.z == 1 ? Wk : Wv);
    float*       out = (blockIdx.z == 0) ? g_q : (blockIdx.z == 1 ? g_k : g_v);

    const int tid = threadIdx.x;
    const int ty  = tid >> 4;      // 0..15 -> 8 rows each
    const int tx  = tid & 15;      // 0..15 -> 4 cols each
    const int m0  = blockIdx.y * 128;
    const int n0  = blockIdx.x * 64;   // head index == blockIdx.x

    float acc[8][4];
    #pragma unroll
    for (int i = 0; i < 8; i++)
        #pragma unroll
        for (int j = 0; j < 4; j++) acc[i][j] = 0.f;

    for (int k0 = 0; k0 < EMBED; k0 += 16) {
        // A: 128x16 -> 512 float4, transposed store
        #pragma unroll
        for (int r = 0; r < 2; r++) {
            int idx = tid + r * 256;
            int row = idx >> 2;
            int c4  = idx & 3;
            float4 v = *(const float4*)&x[(m0 + row) * EMBED + k0 + c4 * 4];
            As[c4*4 + 0][row] = v.x;
            As[c4*4 + 1][row] = v.y;
            As[c4*4 + 2][row] = v.z;
            As[c4*4 + 3][row] = v.w;
        }
        // B: 16x64 -> 256 float4, direct store
        {
            int kk = tid >> 4;
            int n4 = tid & 15;
            *(float4*)&Bs[kk][n4 * 4] =
                *(const float4*)&W[(k0 + kk) * EMBED + n0 + n4 * 4];
        }
        __syncthreads();

        #pragma unroll
        for (int kk = 0; kk < 16; kk++) {
            float4 a0 = *(float4*)&As[kk][ty * 8];
            float4 a1 = *(float4*)&As[kk][ty * 8 + 4];
            float4 b  = *(float4*)&Bs[kk][tx * 4];
            float a[8] = {a0.x, a0.y, a0.z, a0.w, a1.x, a1.y, a1.z, a1.w};
            #pragma unroll
            for (int i = 0; i < 8; i++) {
                acc[i][0] += a[i] * b.x;
                acc[i][1] += a[i] * b.y;
                acc[i][2] += a[i] * b.z;
                acc[i][3] += a[i] * b.w;
            }
        }
        __syncthreads();
    }

    // scatter to [B,H,S,D]; n-tile == one head (64 wide)
    const int h = blockIdx.x;
    #pragma unroll
    for (int i = 0; i < 8; i++) {
        int m = m0 + ty * 8 + i;
        int b = m >> 11;          // /2048
        int s = m & 2047;
        float4 v = make_float4(acc[i][0], acc[i][1], acc[i][2], acc[i][3]);
        *(float4*)&out[(((b * NHEADS + h) * SEQ) + s) * HDIM + tx * 4] = v;
    }
}

// ---------------------------------------------------------------------------
// Flash attention, causal. One CTA = 64 query rows of one (b,h).
// 256 threads as 16x16: thread owns 4 rows x 4 cols (scores) / 4 rows x 4 d (O).
// Warp-shuffle row reductions (lanes 0-15 / 16-31 are independent row groups).
// ---------------------------------------------------------------------------
__global__ __launch_bounds__(256) void attn_kernel()
{
    extern __shared__ float sm[];
    float* Qt = sm;                 // [d][row]  64x68
    float* Kt = Qt + 64 * 68;       // [d][col]  64x68
    float* Vs = Kt + 64 * 68;       // [key][d]  64x68
    float* Ps = Vs + 64 * 68;       // [row][key]64x68

    const int qt = (int)gridDim.x - 1 - (int)blockIdx.x;  // heavy blocks first
    const int bh = blockIdx.y;
    const float* Qg = g_q + (size_t)bh * SEQ * HDIM;
    const float* Kg = g_k + (size_t)bh * SEQ * HDIM;
    const float* Vg = g_v + (size_t)bh * SEQ * HDIM;

    const int tid = threadIdx.x;
    const int ty  = tid >> 4;
    const int tx  = tid & 15;
    const int q0  = qt * 64;

    // load Q tile transposed
    for (int idx = tid; idx < 64 * 16; idx += 256) {
        int row = idx >> 4;
        int c4  = idx & 15;
        float4 v = *(const float4*)&Qg[(q0 + row) * HDIM + c4 * 4];
        Qt[(c4*4 + 0) * 68 + row] = v.x;
        Qt[(c4*4 + 1) * 68 + row] = v.y;
        Qt[(c4*4 + 2) * 68 + row] = v.z;
        Qt[(c4*4 + 3) * 68 + row] = v.w;
    }

    float o[4][4];
    float mrow[4], lrow[4];
    #pragma unroll
    for (int i = 0; i < 4; i++) {
        mrow[i] = -1e30f; lrow[i] = 0.f;
        #pragma unroll
        for (int j = 0; j < 4; j++) o[i][j] = 0.f;
    }
    const float scale = 0.125f;   // 1/sqrt(64)

    for (int kt = 0; kt <= qt; kt++) {
        __syncthreads();   // prev-iter consumers of Kt/Vs/Ps done
        const int k0 = kt * 64;
        for (int idx = tid; idx < 64 * 16; idx += 256) {
            int row = idx >> 4;
            int c4  = idx & 15;
            float4 v = *(const float4*)&Kg[(k0 + row) * HDIM + c4 * 4];
            Kt[(c4*4 + 0) * 68 + row] = v.x;
            Kt[(c4*4 + 1) * 68 + row] = v.y;
            Kt[(c4*4 + 2) * 68 + row] = v.z;
            Kt[(c4*4 + 3) * 68 + row] = v.w;
            float4 w = *(const float4*)&Vg[(k0 + row) * HDIM + c4 * 4];
            *(float4*)&Vs[row * 68 + c4 * 4] = w;
        }
        __syncthreads();

        // S = Q K^T  (4x4 per thread)
        float sc[4][4];
        #pragma unroll
        for (int i = 0; i < 4; i++)
            #pragma unroll
            for (int j = 0; j < 4; j++) sc[i][j] = 0.f;

        #pragma unroll 8
        for (int kk = 0; kk < 64; kk++) {
            float4 a = *(float4*)&Qt[kk * 68 + ty * 4];
            float4 b = *(float4*)&Kt[kk * 68 + tx * 4];
            float av[4] = {a.x, a.y, a.z, a.w};
            #pragma unroll
            for (int i = 0; i < 4; i++) {
                sc[i][0] += av[i] * b.x;
                sc[i][1] += av[i] * b.y;
                sc[i][2] += av[i] * b.z;
                sc[i][3] += av[i] * b.w;
            }
        }

        // scale + causal mask (only the diagonal tile needs masking)
        if (kt == qt) {
            #pragma unroll
            for (int i = 0; i < 4; i++)
                #pragma unroll
                for (int j = 0; j < 4; j++) {
                    int qg = ty * 4 + i;
                    int kg = tx * 4 + j;
                    sc[i][j] = (kg <= qg) ? sc[i][j] * scale : -1e30f;
                }
        } else {
            #pragma unroll
            for (int i = 0; i < 4; i++)
                #pragma unroll
                for (int j = 0; j < 4; j++) sc[i][j] *= scale;
        }

        // online softmax per row (reduce across the 16 tx lanes)
        #pragma unroll
        for (int i = 0; i < 4; i++) {
            float mx = fmaxf(fmaxf(sc[i][0], sc[i][1]), fmaxf(sc[i][2], sc[i][3]));
            #pragma unroll
            for (int off = 1; off < 16; off <<= 1)
                mx = fmaxf(mx, __shfl_xor_sync(0xffffffffu, mx, off));
            float mnew  = fmaxf(mrow[i], mx);
            float alpha = __expf(mrow[i] - mnew);
            mrow[i] = mnew;
            float rs = 0.f;
            #pragma unroll
            for (int j = 0; j < 4; j++) {
                sc[i][j] = __expf(sc[i][j] - mnew);
                rs += sc[i][j];
            }
            #pragma unroll
            for (int off = 1; off < 16; off <<= 1)
                rs += __shfl_xor_sync(0xffffffffu, rs, off);
            lrow[i] = lrow[i] * alpha + rs;
            #pragma unroll
            for (int j = 0; j < 4; j++) o[i][j] *= alpha;
        }

        // publish P
        #pragma unroll
        for (int i = 0; i < 4; i++)
            *(float4*)&Ps[(ty * 4 + i) * 68 + tx * 4] =
                make_float4(sc[i][0], sc[i][1], sc[i][2], sc[i][3]);
        __syncthreads();

        // O += P V
        #pragma unroll 8
        for (int kk = 0; kk < 64; kk++) {
            float4 b = *(float4*)&Vs[kk * 68 + tx * 4];
            #pragma unroll
            for (int i = 0; i < 4; i++) {
                float a = Ps[(ty * 4 + i) * 68 + kk];
                o[i][0] += a * b.x;
                o[i][1] += a * b.y;
                o[i][2] += a * b.z;
                o[i][3] += a * b.w;
            }
        }
    }

    // normalize + store to [B,S,E]
    const int b = bh >> 4;
    const int h = bh & 15;
    #pragma unroll
    for (int i = 0; i < 4; i++) {
        float inv = 1.f / lrow[i];
        int s = q0 + ty * 4 + i;
        float4 v = make_float4(o[i][0]*inv, o[i][1]*inv, o[i][2]*inv, o[i][3]*inv);
        *(float4*)&g_attn[((size_t)b * SEQ + s) * EMBED + h * HDIM + tx * 4] = v;
    }
}

// ---------------------------------------------------------------------------
// Output projection: out = attn @ W_o + b_o  (plain row-major out)
// ---------------------------------------------------------------------------
__global__ __launch_bounds__(256) void oproj_kernel(
    const float* __restrict__ Wo,
    const float* __restrict__ bo,
    float* __restrict__ out)
{
    __shared__ float As[16][132];
    __shared__ float Bs[16][68];

    const int tid = threadIdx.x;
    const int ty  = tid >> 4;
    const int tx  = tid & 15;
    const int m0  = blockIdx.y * 128;
    const int n0  = blockIdx.x * 64;

    float acc[8][4];
    #pragma unroll
    for (int i = 0; i < 8; i++)
        #pragma unroll
        for (int j = 0; j < 4; j++) acc[i][j] = 0.f;

    for (int k0 = 0; k0 < EMBED; k0 += 16) {
        #pragma unroll
        for (int r = 0; r < 2; r++) {
            int idx = tid + r * 256;
            int row = idx >> 2;
            int c4  = idx & 3;
            float4 v = *(const float4*)&g_attn[(size_t)(m0 + row) * EMBED + k0 + c4 * 4];
            As[c4*4 + 0][row] = v.x;
            As[c4*4 + 1][row] = v.y;
            As[c4*4 + 2][row] = v.z;
            As[c4*4 + 3][row] = v.w;
        }
        {
            int kk = tid >> 4;
            int n4 = tid & 15;
            *(float4*)&Bs[kk][n4 * 4] =
                *(const float4*)&Wo[(k0 + kk) * EMBED + n0 + n4 * 4];
        }
        __syncthreads();

        #pragma unroll
        for (int kk = 0; kk < 16; kk++) {
            float4 a0 = *(float4*)&As[kk][ty * 8];
            float4 a1 = *(float4*)&As[kk][ty * 8 + 4];
            float4 b  = *(float4*)&Bs[kk][tx * 4];
            float a[8] = {a0.x, a0.y, a0.z, a0.w, a1.x, a1.y, a1.z, a1.w};
            #pragma unroll
            for (int i = 0; i < 8; i++) {
                acc[i][0] += a[i] * b.x;
                acc[i][1] += a[i] * b.y;
                acc[i][2] += a[i] * b.z;
                acc[i][3] += a[i] * b.w;
            }
        }
        __syncthreads();
    }

    float4 bias = *(const float4*)&bo[n0 + tx * 4];
    #pragma unroll
    for (int i = 0; i < 8; i++) {
        int m = m0 + ty * 8 + i;
        float4 v = make_float4(acc[i][0] + bias.x, acc[i][1] + bias.y,
                               acc[i][2] + bias.z, acc[i][3] + bias.w);
        *(float4*)&out[(size_t)m * EMBED + n0 + tx * 4] = v;
    }
}

// ---------------------------------------------------------------------------
extern "C" void kernel_launch(void* const* d_in, const int* in_sizes, int n_in,
                              void* d_out, int out_size)
{
    const float* x  = (const float*)d_in[0];
    const float* Wq = (const float*)d_in[1];
    const float* Wk = (const float*)d_in[2];
    const float* Wv = (const float*)d_in[3];
    const float* Wo = (const float*)d_in[4];
    const float* bo = (const float*)d_in[5];
    float* out = (float*)d_out;

    const int attn_smem = 4 * 64 * 68 * (int)sizeof(float);   // 69632 B
    cudaFuncSetAttribute(attn_kernel,
                         cudaFuncAttributeMaxDynamicSharedMemorySize, attn_smem);

    // QKV projections: grid (N/64=16 heads, M/128=32, 3 mats)
    qkv_kernel<<<dim3(16, 32, 3), 256>>>(x, Wq, Wk, Wv);

    // Attention: grid (32 q-tiles, 32 bh)
    attn_kernel<<<dim3(32, 32), 256, attn_smem>>>();

    // Output projection: grid (16, 32)
    oproj_kernel<<<dim3(16, 32), 256>>>(Wo, bo, out);
}

// round 5
// speedup vs baseline: 2.4027x; 2.4027x over previous
#include <cuda_runtime.h>
#include <cuda_bf16.h>
#include <cstdint>
#include <math.h>

#define BATCH  2
#define SEQ    2048
#define EMBED  1024
#define NHEADS 16
#define HDIM   64
#define MROWS  4096
#define MATSZ  (MROWS*EMBED)     // 4194304
#define WSZ    (EMBED*EMBED)     // 1048576

// ---------------------------------------------------------------------------
// Scratch planes (__device__ globals; allocation-free rule)
// ---------------------------------------------------------------------------
__device__ __nv_bfloat16 g_xh[MATSZ],  g_xl[MATSZ];     // x split      [M,K]
__device__ __nv_bfloat16 g_wh[4*WSZ],  g_wl[4*WSZ];     // W^T split    [N,K] (q,k,v,o)
__device__ __nv_bfloat16 g_qkvh[3*MATSZ], g_qkvl[3*MATSZ]; // q,k,v [B,H,S,D]
__device__ __nv_bfloat16 g_ah[MATSZ],  g_al[MATSZ];     // attn out     [M,E]

// ---------------------------------------------------------------------------
// Helpers
// ---------------------------------------------------------------------------
__device__ __forceinline__ uint32_t s2u(const void* p){
    uint32_t a;
    asm("{ .reg .u64 t; cvta.to.shared.u64 t, %1; cvt.u32.u64 %0, t; }" : "=r"(a) : "l"(p));
    return a;
}
__device__ __forceinline__ uint32_t pack2(float lo, float hi){
    __nv_bfloat162 v = __halves2bfloat162(__float2bfloat16(lo), __float2bfloat16(hi));
    return *reinterpret_cast<uint32_t*>(&v);
}
__device__ __forceinline__ void ldsm4(uint32_t& r0,uint32_t& r1,uint32_t& r2,uint32_t& r3,uint32_t a){
    asm volatile("ldmatrix.sync.aligned.m8n8.x4.shared.b16 {%0,%1,%2,%3}, [%4];"
        : "=r"(r0),"=r"(r1),"=r"(r2),"=r"(r3) : "r"(a));
}
__device__ __forceinline__ void ldsm4t(uint32_t& r0,uint32_t& r1,uint32_t& r2,uint32_t& r3,uint32_t a){
    asm volatile("ldmatrix.sync.aligned.m8n8.x4.trans.shared.b16 {%0,%1,%2,%3}, [%4];"
        : "=r"(r0),"=r"(r1),"=r"(r2),"=r"(r3) : "r"(a));
}
__device__ __forceinline__ void mma_bf16(float* c, const uint32_t* a, const uint32_t* b){
    asm volatile("mma.sync.aligned.m16n8k16.row.col.f32.bf16.bf16.f32 "
        "{%0,%1,%2,%3}, {%4,%5,%6,%7}, {%8,%9}, {%0,%1,%2,%3};"
        : "+f"(c[0]),"+f"(c[1]),"+f"(c[2]),"+f"(c[3])
        : "r"(a[0]),"r"(a[1]),"r"(a[2]),"r"(a[3]), "r"(b[0]),"r"(b[1]));
}
__device__ __forceinline__ void cpa16(uint32_t dst, const void* src){
    asm volatile("cp.async.cg.shared.global [%0], [%1], 16;" :: "r"(dst), "l"(src));
}
#define CPCOMMIT() asm volatile("cp.async.commit_group;" ::: "memory")
#define CPWAIT0()  asm volatile("cp.async.wait_group 0;" ::: "memory")

// FMA-only exp (x <= 0 path): ~3e-6 rel err, no MUFU.
__device__ __forceinline__ float fexp(float x){
    float y = x * 1.4426950408889634f;
    y = fmaxf(y, -126.0f);
    float t = y + 12582912.0f;               // round-to-nearest
    int   n = __float_as_int(t) - 0x4B400000;
    float f = y - (t - 12582912.0f);         // f in [-0.5, 0.5]
    float p = 1.3333558146e-3f;
    p = fmaf(p, f, 9.6181291076e-3f);
    p = fmaf(p, f, 5.5504108665e-2f);
    p = fmaf(p, f, 2.4022650696e-1f);
    p = fmaf(p, f, 6.9314718056e-1f);
    p = fmaf(p, f, 1.0f);
    return __int_as_float(__float_as_int(p) + (n << 23));
}

// ---------------------------------------------------------------------------
// Prep: split x -> bf16 hi/lo planes
// ---------------------------------------------------------------------------
__global__ __launch_bounds__(256) void splitx_kernel(const float* __restrict__ x)
{
    int i = blockIdx.x*256 + threadIdx.x;    // float4 index, 1048576 total
    float4 v = ((const float4*)x)[i];
    uint32_t h0 = pack2(v.x, v.y), h1 = pack2(v.z, v.w);
    float hx = __uint_as_float(h0 << 16), hy = __uint_as_float(h0 & 0xffff0000u);
    float hz = __uint_as_float(h1 << 16), hw = __uint_as_float(h1 & 0xffff0000u);
    uint32_t l0 = pack2(v.x - hx, v.y - hy), l1 = pack2(v.z - hz, v.w - hw);
    ((uint2*)g_xh)[i] = make_uint2(h0, h1);
    ((uint2*)g_xl)[i] = make_uint2(l0, l1);
}

// ---------------------------------------------------------------------------
// Prep: transpose W [K,N] -> W^T [N,K], split to bf16 hi/lo. z: 0..3 = q,k,v,o
// ---------------------------------------------------------------------------
__global__ __launch_bounds__(256) void wprep_kernel(
    const float* __restrict__ Wq, const float* __restrict__ Wk,
    const float* __restrict__ Wv, const float* __restrict__ Wo)
{
    __shared__ float t[32][33];
    int z = blockIdx.z;
    const float* W = (z==0)?Wq:(z==1)?Wk:(z==2)?Wv:Wo;
    __nv_bfloat16* Oh = g_wh + (size_t)z*WSZ;
    __nv_bfloat16* Ol = g_wl + (size_t)z*WSZ;
    int nb = blockIdx.x*32, kb = blockIdx.y*32;
    int tx = threadIdx.x, ty = threadIdx.y;
    #pragma unroll
    for (int r = 0; r < 4; r++)
        t[ty + r*8][tx] = W[(size_t)(kb + ty + r*8)*EMBED + nb + tx];
    __syncthreads();
    #pragma unroll
    for (int r = 0; r < 4; r++) {
        float v = t[tx][ty + r*8];
        __nv_bfloat16 hb = __float2bfloat16(v);
        size_t o = (size_t)(nb + ty + r*8)*EMBED + kb + tx;
        Oh[o] = hb;
        Ol[o] = __float2bfloat16(v - __bfloat162float(hb));
    }
}

// ---------------------------------------------------------------------------
// mma.sync bf16 3-term split GEMM: D[M,N] = A[M,K] @ B^T[N,K]
// CTA 128x128, 8 warps (4m x 2n), warp 32x64, KC=32, 2-stage cp.async.
// mode 0: A = x planes, B = W_{q,k,v}(z), epilogue -> bf16 hi/lo qkv planes
// mode 1: A = attn planes, B = W_o, epilogue -> fp32 out + bias
// ---------------------------------------------------------------------------
#define GKC 32
#define GPITCH 80
#define GPLANE (128*GPITCH)      // 10240
#define GSTAGE (4*GPLANE)        // 40960
#define GSMEM  (2*GSTAGE)        // 81920

__global__ __launch_bounds__(256,1) void gemm_kernel(float* __restrict__ out,
                                                     const float* __restrict__ bias,
                                                     int mode)
{
    extern __shared__ char smg[];
    const uint32_t sb = s2u(smg);
    const int tid = threadIdx.x, l = tid & 31, wid = tid >> 5;
    const int wm = wid >> 1, wn = wid & 1;
    const int m0 = blockIdx.y * 128, n0 = blockIdx.x * 128;
    const int z = blockIdx.z;

    const __nv_bfloat16 *Ah, *Al, *Bh, *Bl;
    if (mode == 0) {
        Ah = g_xh; Al = g_xl;
        Bh = g_wh + (size_t)z*WSZ; Bl = g_wl + (size_t)z*WSZ;
    } else {
        Ah = g_ah; Al = g_al;
        Bh = g_wh + 3*(size_t)WSZ; Bl = g_wl + 3*(size_t)WSZ;
    }

    auto load_stage = [&](int c){
        const uint32_t sbase = sb + (c & 1)*GSTAGE;
        const int k0 = c * GKC;
        #pragma unroll
        for (int i = 0; i < 8; i++) {
            int g   = i*256 + tid;        // 0..2047
            int p   = g >> 9;             // 0:Ah 1:Al 2:Bh 3:Bl
            int row = (g >> 2) & 127;
            int ch  = g & 3;
            const __nv_bfloat16* src = (p==0)?Ah:(p==1)?Al:(p==2)?Bh:Bl;
            int grow = (p < 2 ? m0 : n0) + row;
            cpa16(sbase + p*GPLANE + row*GPITCH + ch*16,
                  src + (size_t)grow*EMBED + k0 + ch*8);
        }
        CPCOMMIT();
    };

    float acc[2][8][4];
    #pragma unroll
    for (int i = 0; i < 2; i++)
        #pragma unroll
        for (int t = 0; t < 8; t++)
            #pragma unroll
            for (int j = 0; j < 4; j++) acc[i][t][j] = 0.f;

    load_stage(0);
    for (int c = 0; c < 32; c++) {
        CPWAIT0();
        __syncthreads();
        if (c + 1 < 32) load_stage(c + 1);
        const uint32_t stb = sb + (c & 1)*GSTAGE;
        #pragma unroll
        for (int kk = 0; kk < 2; kk++) {
            uint32_t ah[2][4], al[2][4], bhf[8][2], blf[8][2];
            #pragma unroll
            for (int i = 0; i < 2; i++) {
                int row = 32*wm + 16*i + (l & 15);
                int ko  = kk*16 + ((l >> 4) << 3);
                uint32_t off = (uint32_t)(row*GPITCH + ko*2);
                ldsm4(ah[i][0],ah[i][1],ah[i][2],ah[i][3], stb + 0*GPLANE + off);
                ldsm4(al[i][0],al[i][1],al[i][2],al[i][3], stb + 1*GPLANE + off);
            }
            #pragma unroll
            for (int tp = 0; tp < 4; tp++) {
                int nrow = 64*wn + 16*tp + ((l>>4)<<3) + (l & 7);
                int ko   = kk*16 + (((l>>3)&1) << 3);
                uint32_t off = (uint32_t)(nrow*GPITCH + ko*2);
                ldsm4(bhf[2*tp][0],bhf[2*tp][1],bhf[2*tp+1][0],bhf[2*tp+1][1], stb + 2*GPLANE + off);
                ldsm4(blf[2*tp][0],blf[2*tp][1],blf[2*tp+1][0],blf[2*tp+1][1], stb + 3*GPLANE + off);
            }
            // term-major ordering -> long accumulator reuse distance
            #pragma unroll
            for (int i = 0; i < 2; i++)
                #pragma unroll
                for (int t = 0; t < 8; t++) mma_bf16(acc[i][t], ah[i], bhf[t]);
            #pragma unroll
            for (int i = 0; i < 2; i++)
                #pragma unroll
                for (int t = 0; t < 8; t++) mma_bf16(acc[i][t], ah[i], blf[t]);
            #pragma unroll
            for (int i = 0; i < 2; i++)
                #pragma unroll
                for (int t = 0; t < 8; t++) mma_bf16(acc[i][t], al[i], bhf[t]);
        }
    }

    // epilogue
    if (mode == 1) {
        #pragma unroll
        for (int i = 0; i < 2; i++)
            #pragma unroll
            for (int t = 0; t < 8; t++)
                #pragma unroll
                for (int rr = 0; rr < 2; rr++) {
                    int m = m0 + 32*wm + 16*i + (l>>2) + 8*rr;
                    int n = n0 + 64*wn + 8*t + 2*(l&3);
                    float2 v = make_float2(acc[i][t][2*rr]   + bias[n],
                                           acc[i][t][2*rr+1] + bias[n+1]);
                    *(float2*)&out[(size_t)m*EMBED + n] = v;
                }
    } else {
        __nv_bfloat16* oh = g_qkvh + (size_t)z*MATSZ;
        __nv_bfloat16* ol = g_qkvl + (size_t)z*MATSZ;
        const float scl = (z == 0) ? 0.125f : 1.0f;   // fold 1/sqrt(D) into Q
        #pragma unroll
        for (int i = 0; i < 2; i++)
            #pragma unroll
            for (int t = 0; t < 8; t++)
                #pragma unroll
                for (int rr = 0; rr < 2; rr++) {
                    int m = m0 + 32*wm + 16*i + (l>>2) + 8*rr;
                    int n = n0 + 64*wn + 8*t + 2*(l&3);
                    float v0 = acc[i][t][2*rr]*scl, v1 = acc[i][t][2*rr+1]*scl;
                    uint32_t h = pack2(v0, v1);
                    float h0 = __uint_as_float(h << 16);
                    float h1 = __uint_as_float(h & 0xffff0000u);
                    uint32_t lo = pack2(v0 - h0, v1 - h1);
                    int b = m >> 11, s = m & 2047, hh = n >> 6, d = n & 63;
                    size_t idx = ((((size_t)b*NHEADS + hh)*SEQ) + s)*HDIM + d;
                    *(uint32_t*)(oh + idx) = h;
                    *(uint32_t*)(ol + idx) = lo;
                }
    }
}

// ---------------------------------------------------------------------------
// Flash attention via mma.sync. CTA = 128 q-rows of one (b,h); 8 warps = m16 each.
// K-tiles of 64 keys, 2-stage cp.async. P kept in registers (FA2 style).
// ---------------------------------------------------------------------------
#define APITCH 144
#define AQPL   (128*APITCH)        // 18432
#define AKPL   (64*APITCH)         // 9216
#define ASTAGE (4*AKPL)            // 36864
#define ASMEM  (2*AQPL + 2*ASTAGE) // 110592

__global__ __launch_bounds__(256,1) void attn_kernel()
{
    extern __shared__ char sma[];
    const uint32_t sb = s2u(sma);
    const int tid = threadIdx.x, l = tid & 31, wid = tid >> 5;
    const int qt = 15 - (int)blockIdx.x;        // heavy tiles first
    const int bh = blockIdx.y;
    const int q0 = qt * 128;
    const int nkt = 2*qt + 2;
    const size_t base = (size_t)bh * SEQ * HDIM;
    const __nv_bfloat16 *Qh = g_qkvh + base,              *Ql = g_qkvl + base;
    const __nv_bfloat16 *Kh = g_qkvh + MATSZ + base,      *Kl = g_qkvl + MATSZ + base;
    const __nv_bfloat16 *Vh = g_qkvh + 2*(size_t)MATSZ + base,
                        *Vl = g_qkvl + 2*(size_t)MATSZ + base;

    const uint32_t sQh = sb, sQl = sb + AQPL;
    const uint32_t skv0 = sb + 2*AQPL;

    // Q tile loads (128 rows x 2 planes)
    #pragma unroll
    for (int i = 0; i < 8; i++) {
        int g = i*256 + tid;
        int p = g >> 10, row = (g >> 3) & 127, ch = g & 7;
        const __nv_bfloat16* src = p ? Ql : Qh;
        cpa16((p ? sQl : sQh) + row*APITCH + ch*16,
              src + (size_t)(q0 + row)*HDIM + ch*8);
    }
    CPCOMMIT();

    auto load_kv = [&](int kt){
        const uint32_t stb = skv0 + (kt & 1)*ASTAGE;
        const int k0 = kt * 64;
        #pragma unroll
        for (int i = 0; i < 8; i++) {
            int g = i*256 + tid;
            int p = g >> 9, row = (g >> 3) & 63, ch = g & 7;  // p: 0 Kh 1 Kl 2 Vh 3 Vl
            const __nv_bfloat16* src = (p==0)?Kh:(p==1)?Kl:(p==2)?Vh:Vl;
            cpa16(stb + p*AKPL + row*APITCH + ch*16,
                  src + (size_t)(k0 + row)*HDIM + ch*8);
        }
        CPCOMMIT();
    };
    load_kv(0);
    CPWAIT0();
    __syncthreads();

    // Q fragments register-resident (rows 16*wid .. +15, 4 k16 chunks)
    uint32_t qfh[4][4], qfl[4][4];
    {
        int row = 16*wid + (l & 15);
        #pragma unroll
        for (int kc = 0; kc < 4; kc++) {
            int ko = kc*16 + ((l >> 4) << 3);
            uint32_t off = (uint32_t)(row*APITCH + ko*2);
            ldsm4(qfh[kc][0],qfh[kc][1],qfh[kc][2],qfh[kc][3], sQh + off);
            ldsm4(qfl[kc][0],qfl[kc][1],qfl[kc][2],qfl[kc][3], sQl + off);
        }
    }

    float o[8][4];
    #pragma unroll
    for (int t = 0; t < 8; t++)
        #pragma unroll
        for (int j = 0; j < 4; j++) o[t][j] = 0.f;
    float mr0 = -1e30f, mr1 = -1e30f, lr0 = 0.f, lr1 = 0.f;
    const int qg0 = q0 + 16*wid + (l >> 2);
    const int qg1 = qg0 + 8;

    for (int kt = 0; kt < nkt; kt++) {
        if (kt + 1 < nkt) load_kv(kt + 1);
        const uint32_t stb = skv0 + (kt & 1)*ASTAGE;
        const int k0 = kt * 64;

        if (k0 <= q0 + 16*wid + 15) {    // warp not fully masked
            // ---- S = Q K^T (3-term) ----
            float s[8][4];
            #pragma unroll
            for (int t = 0; t < 8; t++)
                #pragma unroll
                for (int j = 0; j < 4; j++) s[t][j] = 0.f;
            #pragma unroll
            for (int kc = 0; kc < 4; kc++) {
                uint32_t bhf[8][2], blf[8][2];
                #pragma unroll
                for (int tp = 0; tp < 4; tp++) {
                    int nrow = 16*tp + ((l>>4)<<3) + (l & 7);
                    int ko   = kc*16 + (((l>>3)&1) << 3);
                    uint32_t off = (uint32_t)(nrow*APITCH + ko*2);
                    ldsm4(bhf[2*tp][0],bhf[2*tp][1],bhf[2*tp+1][0],bhf[2*tp+1][1], stb + 0*AKPL + off);
                    ldsm4(blf[2*tp][0],blf[2*tp][1],blf[2*tp+1][0],blf[2*tp+1][1], stb + 1*AKPL + off);
                }
                #pragma unroll
                for (int t = 0; t < 8; t++) mma_bf16(s[t], qfh[kc], bhf[t]);
                #pragma unroll
                for (int t = 0; t < 8; t++) mma_bf16(s[t], qfh[kc], blf[t]);
                #pragma unroll
                for (int t = 0; t < 8; t++) mma_bf16(s[t], qfl[kc], bhf[t]);
            }
            // ---- causal mask (only near diagonal) ----
            if (k0 + 63 > qg0) {
                #pragma unroll
                for (int t = 0; t < 8; t++) {
                    int kg = k0 + 8*t + 2*(l & 3);
                    if (kg     > qg0) s[t][0] = -1e30f;
                    if (kg + 1 > qg0) s[t][1] = -1e30f;
                    if (kg     > qg1) s[t][2] = -1e30f;
                    if (kg + 1 > qg1) s[t][3] = -1e30f;
                }
            }
            // ---- online softmax (rows qg0, qg1) ----
            float mx0 = -1e30f, mx1 = -1e30f;
            #pragma unroll
            for (int t = 0; t < 8; t++) {
                mx0 = fmaxf(mx0, fmaxf(s[t][0], s[t][1]));
                mx1 = fmaxf(mx1, fmaxf(s[t][2], s[t][3]));
            }
            mx0 = fmaxf(mx0, __shfl_xor_sync(0xffffffffu, mx0, 1));
            mx0 = fmaxf(mx0, __shfl_xor_sync(0xffffffffu, mx0, 2));
            mx1 = fmaxf(mx1, __shfl_xor_sync(0xffffffffu, mx1, 1));
            mx1 = fmaxf(mx1, __shfl_xor_sync(0xffffffffu, mx1, 2));
            float mn0 = fmaxf(mr0, mx0), mn1 = fmaxf(mr1, mx1);
            float a0 = fexp(mr0 - mn0), a1 = fexp(mr1 - mn1);
            mr0 = mn0; mr1 = mn1;
            float rs0 = 0.f, rs1 = 0.f;
            #pragma unroll
            for (int t = 0; t < 8; t++) {
                s[t][0] = fexp(s[t][0] - mn0);
                s[t][1] = fexp(s[t][1] - mn0);
                s[t][2] = fexp(s[t][2] - mn1);
                s[t][3] = fexp(s[t][3] - mn1);
                rs0 += s[t][0] + s[t][1];
                rs1 += s[t][2] + s[t][3];
            }
            rs0 += __shfl_xor_sync(0xffffffffu, rs0, 1);
            rs0 += __shfl_xor_sync(0xffffffffu, rs0, 2);
            rs1 += __shfl_xor_sync(0xffffffffu, rs1, 1);
            rs1 += __shfl_xor_sync(0xffffffffu, rs1, 2);
            lr0 = lr0*a0 + rs0;
            lr1 = lr1*a1 + rs1;
            #pragma unroll
            for (int t = 0; t < 8; t++) {
                o[t][0] *= a0; o[t][1] *= a0; o[t][2] *= a1; o[t][3] *= a1;
            }
            // ---- P -> bf16 hi/lo A-fragments (registers only) ----
            uint32_t ph[4][4], pl[4][4];
            #pragma unroll
            for (int kc = 0; kc < 4; kc++) {
                int t0 = 2*kc, t1 = t0 + 1;
                float pv[4][2] = {{s[t0][0],s[t0][1]},{s[t0][2],s[t0][3]},
                                  {s[t1][0],s[t1][1]},{s[t1][2],s[t1][3]}};
                #pragma unroll
                for (int r = 0; r < 4; r++) {
                    uint32_t h = pack2(pv[r][0], pv[r][1]);
                    float h0 = __uint_as_float(h << 16);
                    float h1 = __uint_as_float(h & 0xffff0000u);
                    ph[kc][r] = h;
                    pl[kc][r] = pack2(pv[r][0] - h0, pv[r][1] - h1);
                }
            }
            // ---- O += P V (3-term), V via ldmatrix.trans ----
            #pragma unroll
            for (int kc = 0; kc < 4; kc++) {
                uint32_t vhf[8][2], vlf[8][2];
                #pragma unroll
                for (int tp = 0; tp < 4; tp++) {
                    int row = kc*16 + ((l>>3)&1)*8 + (l & 7);
                    int co  = 16*tp + ((l >> 4) << 3);
                    uint32_t off = (uint32_t)(row*APITCH + co*2);
                    ldsm4t(vhf[2*tp][0],vhf[2*tp][1],vhf[2*tp+1][0],vhf[2*tp+1][1], stb + 2*AKPL + off);
                    ldsm4t(vlf[2*tp][0],vlf[2*tp][1],vlf[2*tp+1][0],vlf[2*tp+1][1], stb + 3*AKPL + off);
                }
                #pragma unroll
                for (int t = 0; t < 8; t++) mma_bf16(o[t], ph[kc], vhf[t]);
                #pragma unroll
                for (int t = 0; t < 8; t++) mma_bf16(o[t], ph[kc], vlf[t]);
                #pragma unroll
                for (int t = 0; t < 8; t++) mma_bf16(o[t], pl[kc], vhf[t]);
            }
        }
        if (kt + 1 < nkt) { CPWAIT0(); __syncthreads(); }
    }

    // ---- epilogue: normalize, split to bf16 hi/lo, write [B,S,E] planes ----
    const float inv0 = 1.f / lr0, inv1 = 1.f / lr1;
    const int b = bh >> 4, h = bh & 15;
    const int s0 = qg0, s1 = qg1;
    #pragma unroll
    for (int t = 0; t < 8; t++) {
        int d = 8*t + 2*(l & 3);
        int e = h*HDIM + d;
        {
            float v0 = o[t][0]*inv0, v1 = o[t][1]*inv0;
            uint32_t hh = pack2(v0, v1);
            float h0 = __uint_as_float(hh << 16), h1 = __uint_as_float(hh & 0xffff0000u);
            uint32_t ll = pack2(v0 - h0, v1 - h1);
            size_t idx = ((size_t)b*SEQ + s0)*EMBED + e;
            *(uint32_t*)(g_ah + idx) = hh;
            *(uint32_t*)(g_al + idx) = ll;
        }
        {
            float v0 = o[t][2]*inv1, v1 = o[t][3]*inv1;
            uint32_t hh = pack2(v0, v1);
            float h0 = __uint_as_float(hh << 16), h1 = __uint_as_float(hh & 0xffff0000u);
            uint32_t ll = pack2(v0 - h0, v1 - h1);
            size_t idx = ((size_t)b*SEQ + s1)*EMBED + e;
            *(uint32_t*)(g_ah + idx) = hh;
            *(uint32_t*)(g_al + idx) = ll;
        }
    }
}

// ---------------------------------------------------------------------------
extern "C" void kernel_launch(void* const* d_in, const int* in_sizes, int n_in,
                              void* d_out, int out_size)
{
    const float* x  = (const float*)d_in[0];
    const float* Wq = (const float*)d_in[1];
    const float* Wk = (const float*)d_in[2];
    const float* Wv = (const float*)d_in[3];
    const float* Wo = (const float*)d_in[4];
    const float* bo = (const float*)d_in[5];
    float* out = (float*)d_out;

    cudaFuncSetAttribute(gemm_kernel, cudaFuncAttributeMaxDynamicSharedMemorySize, GSMEM);
    cudaFuncSetAttribute(attn_kernel, cudaFuncAttributeMaxDynamicSharedMemorySize, ASMEM);

    splitx_kernel<<<4096, 256>>>(x);
    wprep_kernel<<<dim3(32, 32, 4), dim3(32, 8)>>>(Wq, Wk, Wv, Wo);

    gemm_kernel<<<dim3(8, 32, 3), 256, GSMEM>>>(nullptr, nullptr, 0);  // QKV
    attn_kernel<<<dim3(16, 32), 256, ASMEM>>>();                       // attention
    gemm_kernel<<<dim3(8, 32, 1), 256, GSMEM>>>(out, bo, 1);           // O-proj
}